// round 15
// baseline (speedup 1.0000x reference)
#include <cuda_runtime.h>
#include <cuda_fp16.h>
#include <cstdint>

// SGNS loss, hybrid precision (R13 champion + one change):
//  K1: out_w fp32 -> fp16 scratch. Reads now DEFAULT policy (was evict_first)
//      so non-pinned L2 (~100MB) can retain out_w fp32 across graph replays,
//      cutting the conversion's DRAM reads. (Single-variable A/B vs R13.)
//  K2: main pass, identical to R13: emb fp32 plain __ldg (regs 44, occ 56%),
//      w fp16 scratch pinned evict_last (25.6MB), __stwt output,
//      distributed index fetch, parallel log-sigmoid epilogue.

#define D 128
#define KNEG 5
#define LPP 8          // lanes per pair
#define VMAX 100000

// fp16 mirror of out_w: V*D halves = 25.6MB
__device__ uint4 g_w_h[(size_t)VMAX * D / 8];

__device__ __forceinline__ float log_sigmoid(float x) {
    return fminf(x, 0.0f) - log1pf(__expf(-fabsf(x)));
}

__device__ __forceinline__ uint4 ldg_u4_hint(const void* p, uint64_t pol) {
    uint4 v;
    asm volatile("ld.global.nc.L2::cache_hint.v4.b32 {%0,%1,%2,%3}, [%4], %5;"
                 : "=r"(v.x), "=r"(v.y), "=r"(v.z), "=r"(v.w)
                 : "l"(p), "l"(pol));
    return v;
}

__device__ __forceinline__ uint4 pack8(float4 a, float4 b) {
    uint4 o;
    __half2 h;
    h = __floats2half2_rn(a.x, a.y); o.x = *reinterpret_cast<const uint32_t*>(&h);
    h = __floats2half2_rn(a.z, a.w); o.y = *reinterpret_cast<const uint32_t*>(&h);
    h = __floats2half2_rn(b.x, b.y); o.z = *reinterpret_cast<const uint32_t*>(&h);
    h = __floats2half2_rn(b.z, b.w); o.w = *reinterpret_cast<const uint32_t*>(&h);
    return o;
}

// K1: fp32 -> fp16 conversion of out_w, 8 elements per thread.
// DEFAULT-policy reads: leftover L2 may retain out_w fp32 across replays.
__global__ void __launch_bounds__(256) convert_w_kernel(
    const float* __restrict__ src, int n_elem)
{
    int i = (blockIdx.x * blockDim.x + threadIdx.x) * 8;
    if (i >= n_elem) return;
    float4 a = __ldg(reinterpret_cast<const float4*>(src + i));
    float4 b = __ldg(reinterpret_cast<const float4*>(src + i + 4));
    g_w_h[i >> 3] = pack8(a, b);   // plain store: write-allocate into L2
}

// K2: main SGNS pass (fp32 emb gathers, fp16 w gathers, fp32 accumulate)
__global__ void __launch_bounds__(256) sgns_loss_kernel(
    const float* __restrict__ emb,
    const int*   __restrict__ tgt_ids,
    const int*   __restrict__ ctx_ids,
    const int*   __restrict__ neg_ids,
    float*       __restrict__ out,
    int N)
{
    const int tid  = blockIdx.x * blockDim.x + threadIdx.x;
    const int pair = tid >> 3;
    const int lane = threadIdx.x & (LPP - 1);
    if (pair >= N) return;

    uint64_t pol_last;
    asm("createpolicy.fractional.L2::evict_last.b64 %0, 1.0;" : "=l"(pol_last));

    const unsigned gmask = 0xFFu << ((threadIdx.x & 31) & ~(LPP - 1));

    // Distributed index fetch: slot 0=tgt, 1=ctx, 2..6=neg[0..4]
    int myidx = 0;
    if (lane == 0)      myidx = __ldg(tgt_ids + pair);
    else if (lane == 1) myidx = __ldg(ctx_ids + pair);
    else if (lane < 7)  myidx = __ldg(neg_ids + pair * KNEG + (lane - 2));

    const unsigned t_off = (unsigned)__shfl_sync(gmask, myidx, 0, LPP) << 9;  // fp32 row: 512B
    unsigned roff[1 + KNEG];                                                  // fp16 row: 256B
#pragma unroll
    for (int j = 0; j < 1 + KNEG; j++)
        roff[j] = (unsigned)__shfl_sync(gmask, myidx, 1 + j, LPP) << 8;

    const char* e_b = reinterpret_cast<const char*>(emb);
    const char* w_b = reinterpret_cast<const char*>(g_w_h);
    const unsigned lane16 = (unsigned)lane * 16u;

    // emb gathered in the fp16-dim pattern so lane dim-sets match the w rows:
    // lane l holds dims {8l+64i .. 8l+64i+7}, i=0,1 -> two float4 per chunk.
    float ivf[16];
#pragma unroll
    for (int i = 0; i < 2; i++) {
        float4 p0 = __ldg(reinterpret_cast<const float4*>(e_b + t_off + lane * 32u + 256u * i));
        float4 p1 = __ldg(reinterpret_cast<const float4*>(e_b + t_off + lane * 32u + 256u * i + 16u));
        ivf[i * 8 + 0] = p0.x; ivf[i * 8 + 1] = p0.y;
        ivf[i * 8 + 2] = p0.z; ivf[i * 8 + 3] = p0.w;
        ivf[i * 8 + 4] = p1.x; ivf[i * 8 + 5] = p1.y;
        ivf[i * 8 + 6] = p1.z; ivf[i * 8 + 7] = p1.w;
    }

    // double-buffered walk over the 6 fp16 w rows (evict_last, pinned)
    uint4 cur[2], nxt[2];
#pragma unroll
    for (int i = 0; i < 2; i++)
        cur[i] = ldg_u4_hint(w_b + roff[0] + lane16 + 128u * i, pol_last);

    float s[1 + KNEG];
#pragma unroll
    for (int j = 0; j < 1 + KNEG; j++) {
        if (j < KNEG) {
#pragma unroll
            for (int i = 0; i < 2; i++)
                nxt[i] = ldg_u4_hint(w_b + roff[j + 1] + lane16 + 128u * i, pol_last);
        }
        float acc = 0.f;
#pragma unroll
        for (int i = 0; i < 2; i++) {
            const __half2* h = reinterpret_cast<const __half2*>(&cur[i]);
#pragma unroll
            for (int q = 0; q < 4; q++) {
                float2 f = __half22float2(h[q]);
                acc = fmaf(ivf[i * 8 + q * 2 + 0], f.x, acc);
                acc = fmaf(ivf[i * 8 + q * 2 + 1], f.y, acc);
            }
        }
        s[j] = acc;
        if (j < KNEG) {
            cur[0] = nxt[0];
            cur[1] = nxt[1];
        }
    }

    // 3-stage butterfly: all lanes end with all 6 sums
#pragma unroll
    for (int j = 0; j < 1 + KNEG; j++) {
#pragma unroll
        for (int off = LPP / 2; off > 0; off >>= 1)
            s[j] += __shfl_xor_sync(gmask, s[j], off, LPP);
    }

    // Parallel epilogue: lanes 0..5 each evaluate one log-sigmoid term
    float x = (lane == 0) ? s[0] : -s[lane < 6 ? lane : 0];
    float term = log_sigmoid(x);
    if (lane >= 6) term = 0.f;
#pragma unroll
    for (int off = LPP / 2; off > 0; off >>= 1)
        term += __shfl_xor_sync(gmask, term, off, LPP);

    if (lane == 0)
        __stwt(out + pair, -term);
}

extern "C" void kernel_launch(void* const* d_in, const int* in_sizes, int n_in,
                              void* d_out, int out_size) {
    const float* emb     = (const float*)d_in[0];
    const float* out_w   = (const float*)d_in[1];
    const int*   tgt_ids = (const int*)d_in[2];
    const int*   ctx_ids = (const int*)d_in[3];
    const int*   neg_ids = (const int*)d_in[4];
    float*       out     = (float*)d_out;

    const int n_w = in_sizes[1];              // V * D elements (out_w)
    const int N   = in_sizes[2];              // number of pairs

    // K1: convert out_w -> fp16 (8 elems/thread)
    {
        const int threads = 256;
        const int blocks = (n_w / 8 + threads - 1) / threads;
        convert_w_kernel<<<blocks, threads>>>(out_w, n_w);
    }

    // K2: main pass
    {
        const int threads = 256;               // 32 pairs per block
        const int pairs_per_block = threads / LPP;
        const int blocks = (N + pairs_per_block - 1) / pairs_per_block;
        sgns_loss_kernel<<<blocks, threads>>>(emb, tgt_ids, ctx_ids, neg_ids, out, N);
    }
}

// round 16
// speedup vs baseline: 1.0759x; 1.0759x over previous
#include <cuda_runtime.h>
#include <cuda_fp16.h>
#include <cstdint>

// SGNS loss, hybrid precision (R13 structure, register-pinned):
//  K1: out_w fp32 -> fp16 scratch (8 elems/thread), DEFAULT-policy reads so
//      unpinned L2 (~49MB after the 25.6MB scratch pin + emb pressure) can
//      retain out_w fp32 across graph replays.
//  K2: main pass with __launch_bounds__(256, 5): forces <=48 regs (ptxas had
//      drifted to 58 regs / 44% occ in R14/R15; R13's 44-reg compile ran
//      47.2us vs 49.4us). emb fp32 plain __ldg; w fp16 scratch evict_last;
//      __stwt output; distributed index fetch; parallel logsig epilogue.

#define D 128
#define KNEG 5
#define LPP 8          // lanes per pair
#define VMAX 100000

// fp16 mirror of out_w: V*D halves = 25.6MB
__device__ uint4 g_w_h[(size_t)VMAX * D / 8];

__device__ __forceinline__ float log_sigmoid(float x) {
    return fminf(x, 0.0f) - log1pf(__expf(-fabsf(x)));
}

__device__ __forceinline__ uint4 ldg_u4_hint(const void* p, uint64_t pol) {
    uint4 v;
    asm volatile("ld.global.nc.L2::cache_hint.v4.b32 {%0,%1,%2,%3}, [%4], %5;"
                 : "=r"(v.x), "=r"(v.y), "=r"(v.z), "=r"(v.w)
                 : "l"(p), "l"(pol));
    return v;
}

__device__ __forceinline__ uint4 pack8(float4 a, float4 b) {
    uint4 o;
    __half2 h;
    h = __floats2half2_rn(a.x, a.y); o.x = *reinterpret_cast<const uint32_t*>(&h);
    h = __floats2half2_rn(a.z, a.w); o.y = *reinterpret_cast<const uint32_t*>(&h);
    h = __floats2half2_rn(b.x, b.y); o.z = *reinterpret_cast<const uint32_t*>(&h);
    h = __floats2half2_rn(b.z, b.w); o.w = *reinterpret_cast<const uint32_t*>(&h);
    return o;
}

// K1: fp32 -> fp16 conversion of out_w, 8 elements per thread.
__global__ void __launch_bounds__(256) convert_w_kernel(
    const float* __restrict__ src, int n_elem)
{
    int i = (blockIdx.x * blockDim.x + threadIdx.x) * 8;
    if (i >= n_elem) return;
    float4 a = __ldg(reinterpret_cast<const float4*>(src + i));
    float4 b = __ldg(reinterpret_cast<const float4*>(src + i + 4));
    g_w_h[i >> 3] = pack8(a, b);   // plain store: write-allocate into L2
}

// K2: main SGNS pass (fp32 emb gathers, fp16 w gathers, fp32 accumulate)
__global__ void __launch_bounds__(256, 5) sgns_loss_kernel(
    const float* __restrict__ emb,
    const int*   __restrict__ tgt_ids,
    const int*   __restrict__ ctx_ids,
    const int*   __restrict__ neg_ids,
    float*       __restrict__ out,
    int N)
{
    const int tid  = blockIdx.x * blockDim.x + threadIdx.x;
    const int pair = tid >> 3;
    const int lane = threadIdx.x & (LPP - 1);
    if (pair >= N) return;

    uint64_t pol_last;
    asm("createpolicy.fractional.L2::evict_last.b64 %0, 1.0;" : "=l"(pol_last));

    const unsigned gmask = 0xFFu << ((threadIdx.x & 31) & ~(LPP - 1));

    // Distributed index fetch: slot 0=tgt, 1=ctx, 2..6=neg[0..4]
    int myidx = 0;
    if (lane == 0)      myidx = __ldg(tgt_ids + pair);
    else if (lane == 1) myidx = __ldg(ctx_ids + pair);
    else if (lane < 7)  myidx = __ldg(neg_ids + pair * KNEG + (lane - 2));

    const unsigned t_off = (unsigned)__shfl_sync(gmask, myidx, 0, LPP) << 9;  // fp32 row: 512B
    unsigned roff[1 + KNEG];                                                  // fp16 row: 256B
#pragma unroll
    for (int j = 0; j < 1 + KNEG; j++)
        roff[j] = (unsigned)__shfl_sync(gmask, myidx, 1 + j, LPP) << 8;

    const char* e_b = reinterpret_cast<const char*>(emb);
    const char* w_b = reinterpret_cast<const char*>(g_w_h);
    const unsigned lane16 = (unsigned)lane * 16u;

    // emb gathered in the fp16-dim pattern so lane dim-sets match the w rows:
    // lane l holds dims {8l+64i .. 8l+64i+7}, i=0,1 -> two float4 per chunk.
    float ivf[16];
#pragma unroll
    for (int i = 0; i < 2; i++) {
        float4 p0 = __ldg(reinterpret_cast<const float4*>(e_b + t_off + lane * 32u + 256u * i));
        float4 p1 = __ldg(reinterpret_cast<const float4*>(e_b + t_off + lane * 32u + 256u * i + 16u));
        ivf[i * 8 + 0] = p0.x; ivf[i * 8 + 1] = p0.y;
        ivf[i * 8 + 2] = p0.z; ivf[i * 8 + 3] = p0.w;
        ivf[i * 8 + 4] = p1.x; ivf[i * 8 + 5] = p1.y;
        ivf[i * 8 + 6] = p1.z; ivf[i * 8 + 7] = p1.w;
    }

    // double-buffered walk over the 6 fp16 w rows (evict_last, pinned)
    uint4 cur[2], nxt[2];
#pragma unroll
    for (int i = 0; i < 2; i++)
        cur[i] = ldg_u4_hint(w_b + roff[0] + lane16 + 128u * i, pol_last);

    float s[1 + KNEG];
#pragma unroll
    for (int j = 0; j < 1 + KNEG; j++) {
        if (j < KNEG) {
#pragma unroll
            for (int i = 0; i < 2; i++)
                nxt[i] = ldg_u4_hint(w_b + roff[j + 1] + lane16 + 128u * i, pol_last);
        }
        float acc = 0.f;
#pragma unroll
        for (int i = 0; i < 2; i++) {
            const __half2* h = reinterpret_cast<const __half2*>(&cur[i]);
#pragma unroll
            for (int q = 0; q < 4; q++) {
                float2 f = __half22float2(h[q]);
                acc = fmaf(ivf[i * 8 + q * 2 + 0], f.x, acc);
                acc = fmaf(ivf[i * 8 + q * 2 + 1], f.y, acc);
            }
        }
        s[j] = acc;
        if (j < KNEG) {
            cur[0] = nxt[0];
            cur[1] = nxt[1];
        }
    }

    // 3-stage butterfly: all lanes end with all 6 sums
#pragma unroll
    for (int j = 0; j < 1 + KNEG; j++) {
#pragma unroll
        for (int off = LPP / 2; off > 0; off >>= 1)
            s[j] += __shfl_xor_sync(gmask, s[j], off, LPP);
    }

    // Parallel epilogue: lanes 0..5 each evaluate one log-sigmoid term
    float x = (lane == 0) ? s[0] : -s[lane < 6 ? lane : 0];
    float term = log_sigmoid(x);
    if (lane >= 6) term = 0.f;
#pragma unroll
    for (int off = LPP / 2; off > 0; off >>= 1)
        term += __shfl_xor_sync(gmask, term, off, LPP);

    if (lane == 0)
        __stwt(out + pair, -term);
}

extern "C" void kernel_launch(void* const* d_in, const int* in_sizes, int n_in,
                              void* d_out, int out_size) {
    const float* emb     = (const float*)d_in[0];
    const float* out_w   = (const float*)d_in[1];
    const int*   tgt_ids = (const int*)d_in[2];
    const int*   ctx_ids = (const int*)d_in[3];
    const int*   neg_ids = (const int*)d_in[4];
    float*       out     = (float*)d_out;

    const int n_w = in_sizes[1];              // V * D elements (out_w)
    const int N   = in_sizes[2];              // number of pairs

    // K1: convert out_w -> fp16 (8 elems/thread)
    {
        const int threads = 256;
        const int blocks = (n_w / 8 + threads - 1) / threads;
        convert_w_kernel<<<blocks, threads>>>(out_w, n_w);
    }

    // K2: main pass
    {
        const int threads = 256;               // 32 pairs per block
        const int pairs_per_block = threads / LPP;
        const int blocks = (N + pairs_per_block - 1) / pairs_per_block;
        sgns_loss_kernel<<<blocks, threads>>>(emb, tgt_ids, ctx_ids, neg_ids, out, N);
    }
}

// round 17
// speedup vs baseline: 1.0804x; 1.0042x over previous
#include <cuda_runtime.h>
#include <cuda_fp16.h>
#include <cstdint>

// SGNS loss, hybrid precision, permuted-scratch edition:
//  K1: out_w fp32 -> fp16 scratch with a DIM PERMUTATION: uint4 slot (l,i)
//      of each row holds dims {4l+64i..+3, 4l+64i+32..+35}. This lets the
//      main kernel gather emb with the canonical full-line float4 pattern
//      (dims 4l+32c) while keeping dim-sets matched to the w halves.
//      Conversion reads use evict_first (R13-measured best: keeps churned
//      fp32 out_w from evicting the pinned scratch/emb working set).
//  K2: main pass, __launch_bounds__(256,5) (48 regs / 55% occ, R16-proven):
//      emb 4x full-line LDG.128/pair (was 8 half-line wavefronts),
//      w 2x LDG.128/row evict_last, __stwt out, distributed index fetch,
//      parallel log-sigmoid epilogue.

#define D 128
#define KNEG 5
#define LPP 8          // lanes per pair
#define VMAX 100000

// fp16 mirror of out_w (dim-permuted): V*D halves = 25.6MB
__device__ uint4 g_w_h[(size_t)VMAX * D / 8];

__device__ __forceinline__ float log_sigmoid(float x) {
    return fminf(x, 0.0f) - log1pf(__expf(-fabsf(x)));
}

__device__ __forceinline__ float4 ldg_f4_hint(const void* p, uint64_t pol) {
    float4 v;
    asm volatile("ld.global.nc.L2::cache_hint.v4.f32 {%0,%1,%2,%3}, [%4], %5;"
                 : "=f"(v.x), "=f"(v.y), "=f"(v.z), "=f"(v.w)
                 : "l"(p), "l"(pol));
    return v;
}

__device__ __forceinline__ uint4 ldg_u4_hint(const void* p, uint64_t pol) {
    uint4 v;
    asm volatile("ld.global.nc.L2::cache_hint.v4.b32 {%0,%1,%2,%3}, [%4], %5;"
                 : "=r"(v.x), "=r"(v.y), "=r"(v.z), "=r"(v.w)
                 : "l"(p), "l"(pol));
    return v;
}

__device__ __forceinline__ uint4 pack8(float4 a, float4 b) {
    uint4 o;
    __half2 h;
    h = __floats2half2_rn(a.x, a.y); o.x = *reinterpret_cast<const uint32_t*>(&h);
    h = __floats2half2_rn(a.z, a.w); o.y = *reinterpret_cast<const uint32_t*>(&h);
    h = __floats2half2_rn(b.x, b.y); o.z = *reinterpret_cast<const uint32_t*>(&h);
    h = __floats2half2_rn(b.z, b.w); o.w = *reinterpret_cast<const uint32_t*>(&h);
    return o;
}

// K1: fp32 -> fp16 permuted conversion. One thread per output uint4.
// Thread t: row r = t>>4, slot u = t&15 -> l = u&7, i = u>>3.
// Output halves = dims {4l+64i..+3} ++ {4l+64i+32..+35}.
__global__ void __launch_bounds__(256) convert_w_kernel(
    const float* __restrict__ src, int n_u4)
{
    uint64_t pol_first;
    asm("createpolicy.fractional.L2::evict_first.b64 %0, 1.0;" : "=l"(pol_first));
    int t = blockIdx.x * blockDim.x + threadIdx.x;
    if (t >= n_u4) return;
    const int r = t >> 4;
    const int u = t & 15;
    const int l = u & 7;
    const int i = u >> 3;
    const int f4_base = r * 32 + l + 16 * i;   // float4 index of dims 4l+64i
    float4 a = ldg_f4_hint(reinterpret_cast<const float4*>(src) + f4_base,     pol_first);
    float4 b = ldg_f4_hint(reinterpret_cast<const float4*>(src) + f4_base + 8, pol_first);
    g_w_h[t] = pack8(a, b);
}

// K2: main SGNS pass (fp32 emb gathers, permuted fp16 w gathers)
__global__ void __launch_bounds__(256, 5) sgns_loss_kernel(
    const float* __restrict__ emb,
    const int*   __restrict__ tgt_ids,
    const int*   __restrict__ ctx_ids,
    const int*   __restrict__ neg_ids,
    float*       __restrict__ out,
    int N)
{
    const int tid  = blockIdx.x * blockDim.x + threadIdx.x;
    const int pair = tid >> 3;
    const int lane = threadIdx.x & (LPP - 1);
    if (pair >= N) return;

    uint64_t pol_last;
    asm("createpolicy.fractional.L2::evict_last.b64 %0, 1.0;" : "=l"(pol_last));

    const unsigned gmask = 0xFFu << ((threadIdx.x & 31) & ~(LPP - 1));

    // Distributed index fetch: slot 0=tgt, 1=ctx, 2..6=neg[0..4]
    int myidx = 0;
    if (lane == 0)      myidx = __ldg(tgt_ids + pair);
    else if (lane == 1) myidx = __ldg(ctx_ids + pair);
    else if (lane < 7)  myidx = __ldg(neg_ids + pair * KNEG + (lane - 2));

    const unsigned t_off = (unsigned)__shfl_sync(gmask, myidx, 0, LPP) << 9;  // fp32 row: 512B
    unsigned roff[1 + KNEG];                                                  // fp16 row: 256B
#pragma unroll
    for (int j = 0; j < 1 + KNEG; j++)
        roff[j] = (unsigned)__shfl_sync(gmask, myidx, 1 + j, LPP) << 8;

    const char* e_b = reinterpret_cast<const char*>(emb);
    const char* w_b = reinterpret_cast<const char*>(g_w_h);
    const unsigned lane16 = (unsigned)lane * 16u;

    // emb: canonical full-line pattern, chunk c = float4 at byte 16l + 128c
    //   -> dims 4l+32c .. +3  (4 full-line wavefronts per pair)
    float4 iv[4];
#pragma unroll
    for (int c = 0; c < 4; c++)
        iv[c] = __ldg(reinterpret_cast<const float4*>(e_b + t_off + lane16 + 128u * c));

    // w rows: uint4 slot (l,i) holds dims {4l+64i..+3, 4l+64i+32..+35}
    //   = (iv[2i].xyzw, iv[2i+1].xyzw) -- dim-matched by construction.
    uint4 cur[2], nxt[2];
#pragma unroll
    for (int i = 0; i < 2; i++)
        cur[i] = ldg_u4_hint(w_b + roff[0] + lane16 + 128u * i, pol_last);

    float s[1 + KNEG];
#pragma unroll
    for (int j = 0; j < 1 + KNEG; j++) {
        if (j < KNEG) {
#pragma unroll
            for (int i = 0; i < 2; i++)
                nxt[i] = ldg_u4_hint(w_b + roff[j + 1] + lane16 + 128u * i, pol_last);
        }
        float acc = 0.f;
#pragma unroll
        for (int i = 0; i < 2; i++) {
            const __half2* h = reinterpret_cast<const __half2*>(&cur[i]);
            float2 f0 = __half22float2(h[0]);
            float2 f1 = __half22float2(h[1]);
            float2 f2 = __half22float2(h[2]);
            float2 f3 = __half22float2(h[3]);
            acc = fmaf(iv[2*i].x,   f0.x, acc);
            acc = fmaf(iv[2*i].y,   f0.y, acc);
            acc = fmaf(iv[2*i].z,   f1.x, acc);
            acc = fmaf(iv[2*i].w,   f1.y, acc);
            acc = fmaf(iv[2*i+1].x, f2.x, acc);
            acc = fmaf(iv[2*i+1].y, f2.y, acc);
            acc = fmaf(iv[2*i+1].z, f3.x, acc);
            acc = fmaf(iv[2*i+1].w, f3.y, acc);
        }
        s[j] = acc;
        if (j < KNEG) {
            cur[0] = nxt[0];
            cur[1] = nxt[1];
        }
    }

    // 3-stage butterfly: all lanes end with all 6 sums
#pragma unroll
    for (int j = 0; j < 1 + KNEG; j++) {
#pragma unroll
        for (int off = LPP / 2; off > 0; off >>= 1)
            s[j] += __shfl_xor_sync(gmask, s[j], off, LPP);
    }

    // Parallel epilogue: lanes 0..5 each evaluate one log-sigmoid term
    float x = (lane == 0) ? s[0] : -s[lane < 6 ? lane : 0];
    float term = log_sigmoid(x);
    if (lane >= 6) term = 0.f;
#pragma unroll
    for (int off = LPP / 2; off > 0; off >>= 1)
        term += __shfl_xor_sync(gmask, term, off, LPP);

    if (lane == 0)
        __stwt(out + pair, -term);
}

extern "C" void kernel_launch(void* const* d_in, const int* in_sizes, int n_in,
                              void* d_out, int out_size) {
    const float* emb     = (const float*)d_in[0];
    const float* out_w   = (const float*)d_in[1];
    const int*   tgt_ids = (const int*)d_in[2];
    const int*   ctx_ids = (const int*)d_in[3];
    const int*   neg_ids = (const int*)d_in[4];
    float*       out     = (float*)d_out;

    const int n_w = in_sizes[1];              // V * D elements (out_w)
    const int N   = in_sizes[2];              // number of pairs

    // K1: permuted conversion, one thread per output uint4
    {
        const int n_u4 = n_w / 8;
        const int threads = 256;
        const int blocks = (n_u4 + threads - 1) / threads;
        convert_w_kernel<<<blocks, threads>>>(out_w, n_u4);
    }

    // K2: main pass
    {
        const int threads = 256;               // 32 pairs per block
        const int pairs_per_block = threads / LPP;
        const int blocks = (N + pairs_per_block - 1) / pairs_per_block;
        sgns_loss_kernel<<<blocks, threads>>>(emb, tgt_ids, ctx_ids, neg_ids, out, N);
    }
}